// round 12
// baseline (speedup 1.0000x reference)
#include <cuda_runtime.h>
#include <cuda_fp16.h>
#include <math.h>
#include <stdint.h>

#define BATCH 4
#define SEQ   2048
#define DIM   1024
#define MQ    (BATCH * SEQ)      // 8192

// ---------------------------------------------------------------------------
// Device scratch (no allocation allowed). Single fp16 operands everywhere.
// ---------------------------------------------------------------------------
__device__ float  g_S[BATCH * SEQ * SEQ];            // fp32 scores
__device__ __half g_X [MQ * DIM];
__device__ __half g_Wq[DIM * DIM], g_Wk[DIM * DIM], g_Wv[DIM * DIM];
__device__ __half g_Q [MQ * DIM],  g_K [MQ * DIM];
__device__ __half g_Vt[MQ * DIM];                    // [B][D][S]
__device__ __half g_P [BATCH * SEQ * SEQ];

// ---------------------------------------------------------------------------
// PTX helpers
// ---------------------------------------------------------------------------
__device__ __forceinline__ uint32_t smem_u32(const void* p) {
    uint32_t a;
    asm("{ .reg .u64 t; cvta.to.shared.u64 t, %1; cvt.u32.u64 %0, t; }"
        : "=r"(a) : "l"(p));
    return a;
}

#define CP_ASYNC16(dst, src) \
    asm volatile("cp.async.cg.shared.global [%0], [%1], 16;" :: "r"(dst), "l"(src))
#define CP_COMMIT() asm volatile("cp.async.commit_group;" ::: "memory")
#define CP_WAIT1()  asm volatile("cp.async.wait_group 1;"  ::: "memory")
#define CP_WAIT0()  asm volatile("cp.async.wait_group 0;"  ::: "memory")

#define LDSM_X4(r0, r1, r2, r3, addr) \
    asm volatile("ldmatrix.sync.aligned.m8n8.x4.shared.b16 {%0,%1,%2,%3}, [%4];" \
                 : "=r"(r0), "=r"(r1), "=r"(r2), "=r"(r3) : "r"(addr))

// fp16 inputs, fp32 accumulate
#define MMA16816(d, a, b) \
    asm volatile("mma.sync.aligned.m16n8k16.row.col.f32.f16.f16.f32 " \
                 "{%0,%1,%2,%3},{%4,%5,%6,%7},{%8,%9},{%0,%1,%2,%3};" \
                 : "+f"((d)[0]), "+f"((d)[1]), "+f"((d)[2]), "+f"((d)[3]) \
                 : "r"((a)[0]), "r"((a)[1]), "r"((a)[2]), "r"((a)[3]), \
                   "r"((b)[0]), "r"((b)[1]))

#define SWZ(bo) ((bo) ^ (((bo) >> 3) & 0x70))

// ---------------------------------------------------------------------------
// GEMM: C[M,N] = A[M,K]*B[N,K]^T, fp16 operands, fp32 accumulate.
// CTA tile 128x128, BK=64, 4 warps (warp tile 64x64), 3-stage cp.async pipe.
// Per k16 per warp: 8 ldmatrix.x4 feed 32 MMAs (4 MMA/LDSM).
// EPI: 0=fp32 C; 1=fp16 of acc*escale; 2=transpose fp16 via SMEM stage
// ---------------------------------------------------------------------------
#define STAGES    3
#define TILE_HB   16384                  // one operand tile: 128 rows * 128B
#define STAGE_B   (2 * TILE_HB)          // A + B
#define GSMEM     (STAGES * STAGE_B)     // 96 KB

__device__ __forceinline__ void issue_stage_load(
    uint32_t tile_u,
    const __half* __restrict__ A, const __half* __restrict__ B,
    int m0, int n0, int K, int kc, int t)
{
    const int r = t;                     // 0..127 : one row per thread
#pragma unroll
    for (int c = 0; c < 8; c++) {
        const __half* s = A + (size_t)(m0 + r) * K + kc * 64 + c * 8;
        CP_ASYNC16(tile_u + SWZ((uint32_t)(r * 128 + c * 16)), s);
    }
#pragma unroll
    for (int c = 0; c < 8; c++) {
        const __half* s = B + (size_t)(n0 + r) * K + kc * 64 + c * 8;
        CP_ASYNC16(tile_u + TILE_HB + SWZ((uint32_t)(r * 128 + c * 16)), s);
    }
}

template <int EPI>
__global__ __launch_bounds__(128, 2) void gemm_f16(
    const __half* __restrict__ A, const __half* __restrict__ B,
    float* __restrict__ Cf, __half* __restrict__ Ch,
    int M, int N, int K,
    size_t sA, size_t sB, size_t sC, float escale)
{
    extern __shared__ char smem[];
    const uint32_t sb = smem_u32(smem);
    const int t     = threadIdx.x;
    const int wid   = t >> 5;
    const int lane  = t & 31;
    const int warpm = wid >> 1;          // 0..1
    const int warpn = wid & 1;           // 0..1
    const int m0    = blockIdx.y * 128;
    const int n0    = blockIdx.x * 128;
    const size_t zb = blockIdx.z;

    A += zb * sA;  B += zb * sB;

    float acc[4][8][4];
#pragma unroll
    for (int i = 0; i < 4; i++)
#pragma unroll
        for (int j = 0; j < 8; j++)
#pragma unroll
            for (int c = 0; c < 4; c++) acc[i][j][c] = 0.0f;

    const int nch = K / 64;

    issue_stage_load(sb + 0 * STAGE_B, A, B, m0, n0, K, 0, t);
    CP_COMMIT();
    issue_stage_load(sb + 1 * STAGE_B, A, B, m0, n0, K, 1, t);
    CP_COMMIT();

    // A x4 addressing: lanes 0-15 -> rows, lanes 16-31 -> second k16-half
    const uint32_t a_row  = (uint32_t)(warpm * 64 + (lane & 15));     // + mt*16
    const uint32_t a_k16b = ((lane >> 4) & 1) * 16;
    // B x4 addressing: 4 matrices = 2 n-tiles x 2 k16-halves
    const uint32_t b_row4 = (uint32_t)(warpn * 64 + ((lane >> 4) & 1) * 8 + (lane & 7)); // + np*16
    const uint32_t b_k16b = ((lane >> 3) & 1) * 16;

    for (int kc = 0; kc < nch; kc++) {
        CP_WAIT1();
        __syncthreads();

        if (kc + 2 < nch) {
            issue_stage_load(sb + ((kc + 2) % STAGES) * STAGE_B,
                             A, B, m0, n0, K, kc + 2, t);
        }
        CP_COMMIT();

        const uint32_t tu = sb + (kc % STAGES) * STAGE_B;

#pragma unroll
        for (int k16 = 0; k16 < 4; k16++) {     // 4 x K16 per 64-wide chunk
            uint32_t a[4][4], b[8][2];
#pragma unroll
            for (int mt = 0; mt < 4; mt++) {
                uint32_t bo = (a_row + mt * 16) * 128 + k16 * 32 + a_k16b;
                LDSM_X4(a[mt][0], a[mt][1], a[mt][2], a[mt][3], tu + SWZ(bo));
            }
#pragma unroll
            for (int np = 0; np < 4; np++) {    // each x4 covers 2 n-tiles
                uint32_t bo = (b_row4 + np * 16) * 128 + k16 * 32 + b_k16b;
                LDSM_X4(b[np * 2][0], b[np * 2][1],
                        b[np * 2 + 1][0], b[np * 2 + 1][1],
                        tu + TILE_HB + SWZ(bo));
            }
#pragma unroll
            for (int mt = 0; mt < 4; mt++)
#pragma unroll
                for (int nt = 0; nt < 8; nt++) MMA16816(acc[mt][nt], a[mt], b[nt]);
        }
    }
    CP_WAIT0();

    const int rbase = lane >> 2;           // 0..7
    const int cbase = (lane & 3) * 2;

    if (EPI == 2) {
        // ---- stage transposed tile in SMEM, then coalesced writeout ----
        __syncthreads();
        float* stg = (float*)smem;         // [128 cols][129] fp32 = 66 KB
#pragma unroll
        for (int mt = 0; mt < 4; mt++) {
#pragma unroll
            for (int nt = 0; nt < 8; nt++) {
                int row = warpm * 64 + mt * 16 + rbase;   // s_local
                int col = warpn * 64 + nt * 8 + cbase;    // n_local
                float* d = acc[mt][nt];
                stg[(col + 0) * 129 + row + 0] = d[0];
                stg[(col + 1) * 129 + row + 0] = d[1];
                stg[(col + 0) * 129 + row + 8] = d[2];
                stg[(col + 1) * 129 + row + 8] = d[3];
            }
        }
        __syncthreads();
        const int n_l = t;                 // 0..127
        const int b   = m0 >> 11;
        const int s0  = m0 & 2047;
        const size_t obase = ((size_t)(b * DIM + n0 + n_l)) * SEQ + s0;
#pragma unroll
        for (int j8 = 0; j8 < 16; j8++) {
            ushort hp[8];
#pragma unroll
            for (int e = 0; e < 8; e++) {
                float v = stg[n_l * 129 + j8 * 8 + e] * escale;
                hp[e] = __half_as_ushort(__float2half_rn(v));
            }
            *(uint4*)&Ch[obase + j8 * 8] = *(uint4*)hp;
        }
        return;
    }

#pragma unroll
    for (int mt = 0; mt < 4; mt++) {
#pragma unroll
        for (int nt = 0; nt < 8; nt++) {
            int row = m0 + warpm * 64 + mt * 16 + rbase;
            int col = n0 + warpn * 64 + nt * 8 + cbase;
            float* d = acc[mt][nt];
            if (EPI == 0) {
                float* Cb = Cf + zb * sC;
                *(float2*)&Cb[(size_t)row * N + col]       = make_float2(d[0], d[1]);
                *(float2*)&Cb[(size_t)(row + 8) * N + col] = make_float2(d[2], d[3]);
            } else {   // EPI == 1 : fp16 store
#pragma unroll
                for (int hrow = 0; hrow < 2; hrow++) {
                    __half h0 = __float2half_rn(d[hrow * 2 + 0] * escale);
                    __half h1 = __float2half_rn(d[hrow * 2 + 1] * escale);
                    size_t idx = (size_t)(row + hrow * 8) * N + col;
                    *(uint32_t*)&Ch[idx] = (uint32_t)__half_as_ushort(h0) |
                                           ((uint32_t)__half_as_ushort(h1) << 16);
                }
            }
        }
    }
}

// ---------------------------------------------------------------------------
// fp32 -> fp16 convert (vectorized by 4)
// ---------------------------------------------------------------------------
__global__ __launch_bounds__(256) void cvt_kernel(
    const float* __restrict__ src, __half* __restrict__ dst, int n4)
{
    int i = blockIdx.x * blockDim.x + threadIdx.x;
    if (i >= n4) return;
    float4 x = ((const float4*)src)[i];
    ushort hp[4] = { __half_as_ushort(__float2half_rn(x.x)),
                     __half_as_ushort(__float2half_rn(x.y)),
                     __half_as_ushort(__float2half_rn(x.z)),
                     __half_as_ushort(__float2half_rn(x.w)) };
    ((uint2*)dst)[i] = *(uint2*)hp;
}

// ---------------------------------------------------------------------------
// Softmax over rows of S (pre-scaled via Q), writes P fp16.
// ---------------------------------------------------------------------------
__global__ __launch_bounds__(256) void softmax_kernel(
    const float* __restrict__ S, __half* __restrict__ P)
{
    const float* row = S + (size_t)blockIdx.x * SEQ;
    __half* pr = P + (size_t)blockIdx.x * SEQ;
    const int t = threadIdx.x;
    __shared__ float red[256];

    float v[8];
#pragma unroll
    for (int i = 0; i < 8; i++) v[i] = row[t + i * 256];

    float lmax = v[0];
#pragma unroll
    for (int i = 1; i < 8; i++) lmax = fmaxf(lmax, v[i]);
    red[t] = lmax;
    __syncthreads();
    for (int s = 128; s > 0; s >>= 1) {
        if (t < s) red[t] = fmaxf(red[t], red[t + s]);
        __syncthreads();
    }
    const float m = red[0];
    __syncthreads();

    float lsum = 0.0f;
#pragma unroll
    for (int i = 0; i < 8; i++) { v[i] = __expf(v[i] - m); lsum += v[i]; }
    red[t] = lsum;
    __syncthreads();
    for (int s = 128; s > 0; s >>= 1) {
        if (t < s) red[t] += red[t + s];
        __syncthreads();
    }
    const float inv = 1.0f / red[0];

#pragma unroll
    for (int i = 0; i < 8; i++)
        pr[t + i * 256] = __float2half_rn(v[i] * inv);
}

// ---------------------------------------------------------------------------
// kernel_launch : x, W_key, W_query, W_value -> context (fp32)
// ---------------------------------------------------------------------------
extern "C" void kernel_launch(void* const* d_in, const int* in_sizes, int n_in,
                              void* d_out, int out_size)
{
    const float* x  = (const float*)d_in[0];
    const float* Wk = (const float*)d_in[1];
    const float* Wq = (const float*)d_in[2];
    const float* Wv = (const float*)d_in[3];
    float* out = (float*)d_out;

    float* S;
    __half *X, *Wqh, *Wkh, *Wvh, *Q, *K, *Vt, *P;
    cudaGetSymbolAddress((void**)&S,   g_S);
    cudaGetSymbolAddress((void**)&X,   g_X);
    cudaGetSymbolAddress((void**)&Wqh, g_Wq);
    cudaGetSymbolAddress((void**)&Wkh, g_Wk);
    cudaGetSymbolAddress((void**)&Wvh, g_Wv);
    cudaGetSymbolAddress((void**)&Q,   g_Q);
    cudaGetSymbolAddress((void**)&K,   g_K);
    cudaGetSymbolAddress((void**)&Vt,  g_Vt);
    cudaGetSymbolAddress((void**)&P,   g_P);

    cudaFuncSetAttribute(gemm_f16<0>, cudaFuncAttributeMaxDynamicSharedMemorySize, GSMEM);
    cudaFuncSetAttribute(gemm_f16<1>, cudaFuncAttributeMaxDynamicSharedMemorySize, GSMEM);
    cudaFuncSetAttribute(gemm_f16<2>, cudaFuncAttributeMaxDynamicSharedMemorySize, GSMEM);

    // 1) convert inputs to fp16
    cvt_kernel<<<(MQ * DIM / 4 + 255) / 256, 256>>>(x,  X,   MQ * DIM / 4);
    cvt_kernel<<<(DIM * DIM / 4 + 255) / 256, 256>>>(Wq, Wqh, DIM * DIM / 4);
    cvt_kernel<<<(DIM * DIM / 4 + 255) / 256, 256>>>(Wk, Wkh, DIM * DIM / 4);
    cvt_kernel<<<(DIM * DIM / 4 + 255) / 256, 256>>>(Wv, Wvh, DIM * DIM / 4);

    // 2) projections: Q (scaled by 1/32), K, V (transpose-store)
    {
        dim3 grid(DIM / 128, MQ / 128, 1);
        gemm_f16<1><<<grid, 128, GSMEM>>>(X, Wqh, nullptr, Q,
            MQ, DIM, DIM, 0, 0, 0, 1.0f / 32.0f);
        gemm_f16<1><<<grid, 128, GSMEM>>>(X, Wkh, nullptr, K,
            MQ, DIM, DIM, 0, 0, 0, 1.0f);
        gemm_f16<2><<<grid, 128, GSMEM>>>(X, Wvh, nullptr, Vt,
            MQ, DIM, DIM, 0, 0, 0, 1.0f);
    }

    // 3) scores[b] = Qs[b] * K[b]^T  (already scaled) -> fp32 S
    {
        dim3 grid(SEQ / 128, SEQ / 128, BATCH);
        gemm_f16<0><<<grid, 128, GSMEM>>>(Q, K, S, nullptr,
            SEQ, SEQ, DIM,
            (size_t)SEQ * DIM, (size_t)SEQ * DIM, (size_t)SEQ * SEQ, 1.0f);
    }

    // 4) softmax rows -> P fp16
    softmax_kernel<<<BATCH * SEQ, 256>>>(S, P);

    // 5) context[b] = P[b] * Vt[b]^T -> out fp32
    {
        dim3 grid(DIM / 128, SEQ / 128, BATCH);
        gemm_f16<0><<<grid, 128, GSMEM>>>(P, Vt, out, nullptr,
            SEQ, DIM, SEQ,
            (size_t)SEQ * SEQ, (size_t)DIM * SEQ, (size_t)SEQ * DIM, 1.0f);
    }
}

// round 14
// speedup vs baseline: 2.1535x; 2.1535x over previous
#include <cuda_runtime.h>
#include <cuda_fp16.h>
#include <math.h>
#include <stdint.h>

#define BATCH 4
#define SEQ   2048
#define DIM   1024
#define MQ    (BATCH * SEQ)      // 8192

// ---------------------------------------------------------------------------
// Device scratch (no allocation allowed). Single fp16 operands everywhere.
// ---------------------------------------------------------------------------
__device__ float  g_S[BATCH * SEQ * SEQ];            // fp32 scores
__device__ __half g_X [MQ * DIM];
__device__ __half g_Wq[DIM * DIM], g_Wk[DIM * DIM], g_Wv[DIM * DIM];
__device__ __half g_Q [MQ * DIM],  g_K [MQ * DIM];
__device__ __half g_Vt[MQ * DIM];                    // [B][D][S]
__device__ __half g_P [BATCH * SEQ * SEQ];

// ---------------------------------------------------------------------------
// PTX helpers
// ---------------------------------------------------------------------------
__device__ __forceinline__ uint32_t smem_u32(const void* p) {
    uint32_t a;
    asm("{ .reg .u64 t; cvta.to.shared.u64 t, %1; cvt.u32.u64 %0, t; }"
        : "=r"(a) : "l"(p));
    return a;
}

#define CP_ASYNC16(dst, src) \
    asm volatile("cp.async.cg.shared.global [%0], [%1], 16;" :: "r"(dst), "l"(src))
#define CP_COMMIT() asm volatile("cp.async.commit_group;" ::: "memory")
#define CP_WAIT1()  asm volatile("cp.async.wait_group 1;"  ::: "memory")
#define CP_WAIT0()  asm volatile("cp.async.wait_group 0;"  ::: "memory")

#define LDSM_X4(r0, r1, r2, r3, addr) \
    asm volatile("ldmatrix.sync.aligned.m8n8.x4.shared.b16 {%0,%1,%2,%3}, [%4];" \
                 : "=r"(r0), "=r"(r1), "=r"(r2), "=r"(r3) : "r"(addr))

// fp16 inputs, fp32 accumulate
#define MMA16816(d, a, b) \
    asm volatile("mma.sync.aligned.m16n8k16.row.col.f32.f16.f16.f32 " \
                 "{%0,%1,%2,%3},{%4,%5,%6,%7},{%8,%9},{%0,%1,%2,%3};" \
                 : "+f"((d)[0]), "+f"((d)[1]), "+f"((d)[2]), "+f"((d)[3]) \
                 : "r"((a)[0]), "r"((a)[1]), "r"((a)[2]), "r"((a)[3]), \
                   "r"((b)[0]), "r"((b)[1]))

#define SWZ(bo) ((bo) ^ (((bo) >> 3) & 0x70))

// ---------------------------------------------------------------------------
// GEMM: C[M,N] = A[M,K]*B[N,K]^T, fp16 operands, fp32 accumulate.
// CTA tile 128x128, BK=64, 8 warps (warp tile 64x32 — PROVEN config),
// 3-stage cp.async pipeline, one __syncthreads per iteration.
// B fragments fetched with ldmatrix.x4 (2 n-tiles per load).
// EPI: 0=fp32 C; 1=fp16 of acc*escale; 2=transpose fp16 via SMEM stage
// ---------------------------------------------------------------------------
#define STAGES    3
#define TILE_HB   16384                  // one operand tile: 128 rows * 128B
#define STAGE_B   (2 * TILE_HB)          // A + B
#define GSMEM     (STAGES * STAGE_B)     // 96 KB

__device__ __forceinline__ void issue_stage_load(
    uint32_t tile_u,
    const __half* __restrict__ A, const __half* __restrict__ B,
    int m0, int n0, int K, int kc, int t)
{
    const int r = t >> 1;                // 0..127
    const int h = t & 1;
#pragma unroll
    for (int c = 0; c < 4; c++) {
        int c8 = h * 4 + c;              // 0..7, 16B chunks covering 64 fp16
        const __half* s = A + (size_t)(m0 + r) * K + kc * 64 + c8 * 8;
        CP_ASYNC16(tile_u + SWZ((uint32_t)(r * 128 + c8 * 16)), s);
    }
#pragma unroll
    for (int c = 0; c < 4; c++) {
        int c8 = h * 4 + c;
        const __half* s = B + (size_t)(n0 + r) * K + kc * 64 + c8 * 8;
        CP_ASYNC16(tile_u + TILE_HB + SWZ((uint32_t)(r * 128 + c8 * 16)), s);
    }
}

template <int EPI>
__global__ __launch_bounds__(256, 2) void gemm_f16(
    const __half* __restrict__ A, const __half* __restrict__ B,
    float* __restrict__ Cf, __half* __restrict__ Ch,
    int M, int N, int K,
    size_t sA, size_t sB, size_t sC, float escale)
{
    extern __shared__ char smem[];
    const uint32_t sb = smem_u32(smem);
    const int t     = threadIdx.x;
    const int wid   = t >> 5;
    const int lane  = t & 31;
    const int warpm = wid >> 2;          // 0..1
    const int warpn = wid & 3;           // 0..3
    const int m0    = blockIdx.y * 128;
    const int n0    = blockIdx.x * 128;
    const size_t zb = blockIdx.z;

    A += zb * sA;  B += zb * sB;

    float acc[4][4][4];
#pragma unroll
    for (int i = 0; i < 4; i++)
#pragma unroll
        for (int j = 0; j < 4; j++)
#pragma unroll
            for (int c = 0; c < 4; c++) acc[i][j][c] = 0.0f;

    const int nch = K / 64;

    issue_stage_load(sb + 0 * STAGE_B, A, B, m0, n0, K, 0, t);
    CP_COMMIT();
    issue_stage_load(sb + 1 * STAGE_B, A, B, m0, n0, K, 1, t);
    CP_COMMIT();

    // A x4 addressing
    const uint32_t a_row  = (uint32_t)(warpm * 64 + (lane & 15));   // + mt*16
    const uint32_t a_k16b = ((lane >> 4) & 1) * 16;
    // B x4 addressing: each x4 = 2 n-tiles x 2 k16-halves
    const uint32_t b_row4 = (uint32_t)(warpn * 32 + ((lane >> 4) & 1) * 8 + (lane & 7)); // + np*16
    const uint32_t b_k16b = ((lane >> 3) & 1) * 16;

    for (int kc = 0; kc < nch; kc++) {
        CP_WAIT1();
        __syncthreads();

        if (kc + 2 < nch) {
            issue_stage_load(sb + ((kc + 2) % STAGES) * STAGE_B,
                             A, B, m0, n0, K, kc + 2, t);
        }
        CP_COMMIT();

        const uint32_t tu = sb + (kc % STAGES) * STAGE_B;

#pragma unroll
        for (int k16 = 0; k16 < 4; k16++) {     // 4 x K16 per 64-wide chunk
            uint32_t a[4][4], b[4][2];
#pragma unroll
            for (int mt = 0; mt < 4; mt++) {
                uint32_t bo = (a_row + mt * 16) * 128 + k16 * 32 + a_k16b;
                LDSM_X4(a[mt][0], a[mt][1], a[mt][2], a[mt][3], tu + SWZ(bo));
            }
#pragma unroll
            for (int np = 0; np < 2; np++) {    // each x4 covers 2 n-tiles
                uint32_t bo = (b_row4 + np * 16) * 128 + k16 * 32 + b_k16b;
                LDSM_X4(b[np * 2][0], b[np * 2][1],
                        b[np * 2 + 1][0], b[np * 2 + 1][1],
                        tu + TILE_HB + SWZ(bo));
            }
#pragma unroll
            for (int mt = 0; mt < 4; mt++)
#pragma unroll
                for (int nt = 0; nt < 4; nt++) MMA16816(acc[mt][nt], a[mt], b[nt]);
        }
    }
    CP_WAIT0();

    const int rbase = lane >> 2;           // 0..7
    const int cbase = (lane & 3) * 2;

    if (EPI == 2) {
        // ---- stage transposed tile in SMEM, then coalesced writeout ----
        __syncthreads();
        float* stg = (float*)smem;         // [128 cols][129] fp32 = 66 KB
#pragma unroll
        for (int mt = 0; mt < 4; mt++) {
#pragma unroll
            for (int nt = 0; nt < 4; nt++) {
                int row = warpm * 64 + mt * 16 + rbase;   // s_local
                int col = warpn * 32 + nt * 8 + cbase;    // n_local
                float* d = acc[mt][nt];
                stg[(col + 0) * 129 + row + 0] = d[0];
                stg[(col + 1) * 129 + row + 0] = d[1];
                stg[(col + 0) * 129 + row + 8] = d[2];
                stg[(col + 1) * 129 + row + 8] = d[3];
            }
        }
        __syncthreads();
        const int n_l = t >> 1;            // 0..127
        const int hf  = t & 1;
        const int b   = m0 >> 11;
        const int s0  = (m0 & 2047) + hf * 64;
        const size_t obase = ((size_t)(b * DIM + n0 + n_l)) * SEQ + s0;
#pragma unroll
        for (int j8 = 0; j8 < 8; j8++) {
            ushort hp[8];
#pragma unroll
            for (int e = 0; e < 8; e++) {
                float v = stg[n_l * 129 + hf * 64 + j8 * 8 + e] * escale;
                hp[e] = __half_as_ushort(__float2half_rn(v));
            }
            *(uint4*)&Ch[obase + j8 * 8] = *(uint4*)hp;
        }
        return;
    }

#pragma unroll
    for (int mt = 0; mt < 4; mt++) {
#pragma unroll
        for (int nt = 0; nt < 4; nt++) {
            int row = m0 + warpm * 64 + mt * 16 + rbase;
            int col = n0 + warpn * 32 + nt * 8 + cbase;
            float* d = acc[mt][nt];
            if (EPI == 0) {
                float* Cb = Cf + zb * sC;
                *(float2*)&Cb[(size_t)row * N + col]       = make_float2(d[0], d[1]);
                *(float2*)&Cb[(size_t)(row + 8) * N + col] = make_float2(d[2], d[3]);
            } else {   // EPI == 1 : fp16 store
#pragma unroll
                for (int hrow = 0; hrow < 2; hrow++) {
                    __half h0 = __float2half_rn(d[hrow * 2 + 0] * escale);
                    __half h1 = __float2half_rn(d[hrow * 2 + 1] * escale);
                    size_t idx = (size_t)(row + hrow * 8) * N + col;
                    *(uint32_t*)&Ch[idx] = (uint32_t)__half_as_ushort(h0) |
                                           ((uint32_t)__half_as_ushort(h1) << 16);
                }
            }
        }
    }
}

// ---------------------------------------------------------------------------
// Fused fp32 -> fp16 convert for all 4 inputs in ONE launch.
// Layout: [X : MQ*DIM][Wq : DIM*DIM][Wk][Wv], each /4 float4 granules.
// ---------------------------------------------------------------------------
#define N4_X  (MQ * DIM / 4)
#define N4_W  (DIM * DIM / 4)

__global__ __launch_bounds__(256) void cvt_all_kernel(
    const float* __restrict__ x,  const float* __restrict__ wq,
    const float* __restrict__ wk, const float* __restrict__ wv,
    __half* __restrict__ X,  __half* __restrict__ Wq,
    __half* __restrict__ Wk, __half* __restrict__ Wv)
{
    int i = blockIdx.x * blockDim.x + threadIdx.x;
    const float* src;  __half* dst;  int j = i;
    if (j < N4_X)                { src = x;  dst = X;  }
    else if ((j -= N4_X) < N4_W) { src = wq; dst = Wq; }
    else if ((j -= N4_W) < N4_W) { src = wk; dst = Wk; }
    else if ((j -= N4_W) < N4_W) { src = wv; dst = Wv; }
    else return;
    float4 v = ((const float4*)src)[j];
    ushort hp[4] = { __half_as_ushort(__float2half_rn(v.x)),
                     __half_as_ushort(__float2half_rn(v.y)),
                     __half_as_ushort(__float2half_rn(v.z)),
                     __half_as_ushort(__float2half_rn(v.w)) };
    ((uint2*)dst)[j] = *(uint2*)hp;
}

// ---------------------------------------------------------------------------
// Softmax over rows of S (pre-scaled via Q), writes P fp16. float4 loads.
// One block (256 threads) per row of 2048; each thread owns 8 contiguous-by-4.
// ---------------------------------------------------------------------------
__global__ __launch_bounds__(256) void softmax_kernel(
    const float* __restrict__ S, __half* __restrict__ P)
{
    const float4* row = (const float4*)(S + (size_t)blockIdx.x * SEQ);
    __half* pr = P + (size_t)blockIdx.x * SEQ;
    const int t = threadIdx.x;
    __shared__ float red[256];

    float4 v0 = row[t];            // elems 4t..4t+3
    float4 v1 = row[256 + t];      // elems 1024+4t..

    float lmax = fmaxf(fmaxf(fmaxf(v0.x, v0.y), fmaxf(v0.z, v0.w)),
                       fmaxf(fmaxf(v1.x, v1.y), fmaxf(v1.z, v1.w)));
    red[t] = lmax;
    __syncthreads();
    for (int s = 128; s > 0; s >>= 1) {
        if (t < s) red[t] = fmaxf(red[t], red[t + s]);
        __syncthreads();
    }
    const float m = red[0];
    __syncthreads();

    v0.x = __expf(v0.x - m);  v0.y = __expf(v0.y - m);
    v0.z = __expf(v0.z - m);  v0.w = __expf(v0.w - m);
    v1.x = __expf(v1.x - m);  v1.y = __expf(v1.y - m);
    v1.z = __expf(v1.z - m);  v1.w = __expf(v1.w - m);
    float lsum = (v0.x + v0.y) + (v0.z + v0.w) + (v1.x + v1.y) + (v1.z + v1.w);
    red[t] = lsum;
    __syncthreads();
    for (int s = 128; s > 0; s >>= 1) {
        if (t < s) red[t] += red[t + s];
        __syncthreads();
    }
    const float inv = 1.0f / red[0];

    ushort h0[4] = { __half_as_ushort(__float2half_rn(v0.x * inv)),
                     __half_as_ushort(__float2half_rn(v0.y * inv)),
                     __half_as_ushort(__float2half_rn(v0.z * inv)),
                     __half_as_ushort(__float2half_rn(v0.w * inv)) };
    ushort h1[4] = { __half_as_ushort(__float2half_rn(v1.x * inv)),
                     __half_as_ushort(__float2half_rn(v1.y * inv)),
                     __half_as_ushort(__float2half_rn(v1.z * inv)),
                     __half_as_ushort(__float2half_rn(v1.w * inv)) };
    ((uint2*)pr)[t]       = *(uint2*)h0;
    ((uint2*)pr)[256 + t] = *(uint2*)h1;
}

// ---------------------------------------------------------------------------
// kernel_launch : x, W_key, W_query, W_value -> context (fp32)
// ---------------------------------------------------------------------------
extern "C" void kernel_launch(void* const* d_in, const int* in_sizes, int n_in,
                              void* d_out, int out_size)
{
    const float* x  = (const float*)d_in[0];
    const float* Wk = (const float*)d_in[1];
    const float* Wq = (const float*)d_in[2];
    const float* Wv = (const float*)d_in[3];
    float* out = (float*)d_out;

    float* S;
    __half *X, *Wqh, *Wkh, *Wvh, *Q, *K, *Vt, *P;
    cudaGetSymbolAddress((void**)&S,   g_S);
    cudaGetSymbolAddress((void**)&X,   g_X);
    cudaGetSymbolAddress((void**)&Wqh, g_Wq);
    cudaGetSymbolAddress((void**)&Wkh, g_Wk);
    cudaGetSymbolAddress((void**)&Wvh, g_Wv);
    cudaGetSymbolAddress((void**)&Q,   g_Q);
    cudaGetSymbolAddress((void**)&K,   g_K);
    cudaGetSymbolAddress((void**)&Vt,  g_Vt);
    cudaGetSymbolAddress((void**)&P,   g_P);

    cudaFuncSetAttribute(gemm_f16<0>, cudaFuncAttributeMaxDynamicSharedMemorySize, GSMEM);
    cudaFuncSetAttribute(gemm_f16<1>, cudaFuncAttributeMaxDynamicSharedMemorySize, GSMEM);
    cudaFuncSetAttribute(gemm_f16<2>, cudaFuncAttributeMaxDynamicSharedMemorySize, GSMEM);

    // 1) convert all inputs to fp16 in one launch
    {
        int total = N4_X + 3 * N4_W;
        cvt_all_kernel<<<(total + 255) / 256, 256>>>(x, Wq, Wk, Wv,
                                                     X, Wqh, Wkh, Wvh);
    }

    // 2) projections: Q (scaled by 1/32), K, V (transpose-store)
    {
        dim3 grid(DIM / 128, MQ / 128, 1);
        gemm_f16<1><<<grid, 256, GSMEM>>>(X, Wqh, nullptr, Q,
            MQ, DIM, DIM, 0, 0, 0, 1.0f / 32.0f);
        gemm_f16<1><<<grid, 256, GSMEM>>>(X, Wkh, nullptr, K,
            MQ, DIM, DIM, 0, 0, 0, 1.0f);
        gemm_f16<2><<<grid, 256, GSMEM>>>(X, Wvh, nullptr, Vt,
            MQ, DIM, DIM, 0, 0, 0, 1.0f);
    }

    // 3) scores[b] = Qs[b] * K[b]^T  (already scaled) -> fp32 S
    {
        dim3 grid(SEQ / 128, SEQ / 128, BATCH);
        gemm_f16<0><<<grid, 256, GSMEM>>>(Q, K, S, nullptr,
            SEQ, SEQ, DIM,
            (size_t)SEQ * DIM, (size_t)SEQ * DIM, (size_t)SEQ * SEQ, 1.0f);
    }

    // 4) softmax rows -> P fp16
    softmax_kernel<<<BATCH * SEQ, 256>>>(S, P);

    // 5) context[b] = P[b] * Vt[b]^T -> out fp32
    {
        dim3 grid(DIM / 128, SEQ / 128, BATCH);
        gemm_f16<0><<<grid, 256, GSMEM>>>(P, Vt, out, nullptr,
            SEQ, DIM, SEQ,
            (size_t)SEQ * SEQ, (size_t)DIM * SEQ, (size_t)SEQ * DIM, 1.0f);
    }
}

// round 16
// speedup vs baseline: 2.2625x; 1.0506x over previous
#include <cuda_runtime.h>
#include <cuda_fp16.h>
#include <math.h>
#include <stdint.h>

#define BATCH 4
#define SEQ   2048
#define DIM   1024
#define MQ    (BATCH * SEQ)      // 8192

// ---------------------------------------------------------------------------
// Device scratch (no allocation allowed). Single fp16 operands everywhere.
// ---------------------------------------------------------------------------
__device__ float  g_S[BATCH * SEQ * SEQ];            // fp32 scores
__device__ __half g_X [MQ * DIM];
__device__ __half g_Wq[DIM * DIM], g_Wk[DIM * DIM], g_Wv[DIM * DIM];
__device__ __half g_Q [MQ * DIM],  g_K [MQ * DIM];
__device__ __half g_Vt[MQ * DIM];                    // [B][D][S]
__device__ __half g_P [BATCH * SEQ * SEQ];

// ---------------------------------------------------------------------------
// PTX helpers
// ---------------------------------------------------------------------------
__device__ __forceinline__ uint32_t smem_u32(const void* p) {
    uint32_t a;
    asm("{ .reg .u64 t; cvta.to.shared.u64 t, %1; cvt.u32.u64 %0, t; }"
        : "=r"(a) : "l"(p));
    return a;
}

#define CP_ASYNC16(dst, src) \
    asm volatile("cp.async.cg.shared.global [%0], [%1], 16;" :: "r"(dst), "l"(src))
#define CP_COMMIT() asm volatile("cp.async.commit_group;" ::: "memory")
#define CP_WAIT1()  asm volatile("cp.async.wait_group 1;"  ::: "memory")
#define CP_WAIT0()  asm volatile("cp.async.wait_group 0;"  ::: "memory")

#define LDSM_X4(r0, r1, r2, r3, addr) \
    asm volatile("ldmatrix.sync.aligned.m8n8.x4.shared.b16 {%0,%1,%2,%3}, [%4];" \
                 : "=r"(r0), "=r"(r1), "=r"(r2), "=r"(r3) : "r"(addr))

// fp16 inputs, fp32 accumulate
#define MMA16816(d, a, b) \
    asm volatile("mma.sync.aligned.m16n8k16.row.col.f32.f16.f16.f32 " \
                 "{%0,%1,%2,%3},{%4,%5,%6,%7},{%8,%9},{%0,%1,%2,%3};" \
                 : "+f"((d)[0]), "+f"((d)[1]), "+f"((d)[2]), "+f"((d)[3]) \
                 : "r"((a)[0]), "r"((a)[1]), "r"((a)[2]), "r"((a)[3]), \
                   "r"((b)[0]), "r"((b)[1]))

#define SWZ(bo) ((bo) ^ (((bo) >> 3) & 0x70))

// ---------------------------------------------------------------------------
// GEMM: C[M,N] = A[M,K]*B[N,K]^T, fp16 operands, fp32 accumulate.
// CTA tile 128x64, BK=64, 8 warps (warp tile 32x32), 3-stage cp.async pipe.
// Low-register config (acc=32/thread) targeting 3 CTAs/SM (24 warps).
// EPI: 0=fp32 C; 1=fp16 of acc*escale; 2=transpose fp16 via SMEM stage
// ---------------------------------------------------------------------------
#define STAGES    3
#define TILE_A_B  16384                  // A tile: 128 rows * 128B
#define TILE_B_B  8192                   // B tile:  64 rows * 128B
#define STAGE_B   (TILE_A_B + TILE_B_B)  // 24 KB
#define GSMEM     (STAGES * STAGE_B)     // 72 KB

__device__ __forceinline__ void issue_stage_load(
    uint32_t tile_u,
    const __half* __restrict__ A, const __half* __restrict__ B,
    int m0, int n0, int K, int kc, int t)
{
    // A: 128 rows x 8 chunks = 1024 slots / 256 thr = 4 each
    {
        const int r = t >> 1;            // 0..127
        const int h = t & 1;
#pragma unroll
        for (int c = 0; c < 4; c++) {
            int c8 = h * 4 + c;
            const __half* s = A + (size_t)(m0 + r) * K + kc * 64 + c8 * 8;
            CP_ASYNC16(tile_u + SWZ((uint32_t)(r * 128 + c8 * 16)), s);
        }
    }
    // B: 64 rows x 8 chunks = 512 slots / 256 thr = 2 each
    {
#pragma unroll
        for (int i = 0; i < 2; i++) {
            int f  = t * 2 + i;          // 0..511
            int r  = f >> 3;             // 0..63
            int c8 = f & 7;
            const __half* s = B + (size_t)(n0 + r) * K + kc * 64 + c8 * 8;
            CP_ASYNC16(tile_u + TILE_A_B + SWZ((uint32_t)(r * 128 + c8 * 16)), s);
        }
    }
}

template <int EPI>
__global__ __launch_bounds__(256, 3) void gemm_f16(
    const __half* __restrict__ A, const __half* __restrict__ B,
    float* __restrict__ Cf, __half* __restrict__ Ch,
    int M, int N, int K,
    size_t sA, size_t sB, size_t sC, float escale)
{
    extern __shared__ char smem[];
    const uint32_t sb = smem_u32(smem);
    const int t     = threadIdx.x;
    const int wid   = t >> 5;
    const int lane  = t & 31;
    const int warpm = wid >> 1;          // 0..3  (32-row bands)
    const int warpn = wid & 1;           // 0..1  (32-col bands)
    const int m0    = blockIdx.y * 128;
    const int n0    = blockIdx.x * 64;
    const size_t zb = blockIdx.z;

    A += zb * sA;  B += zb * sB;

    float acc[2][4][4];
#pragma unroll
    for (int i = 0; i < 2; i++)
#pragma unroll
        for (int j = 0; j < 4; j++)
#pragma unroll
            for (int c = 0; c < 4; c++) acc[i][j][c] = 0.0f;

    const int nch = K / 64;

    issue_stage_load(sb + 0 * STAGE_B, A, B, m0, n0, K, 0, t);
    CP_COMMIT();
    issue_stage_load(sb + 1 * STAGE_B, A, B, m0, n0, K, 1, t);
    CP_COMMIT();

    // A x4 addressing (2 m-tiles per warp)
    const uint32_t a_row  = (uint32_t)(warpm * 32 + (lane & 15));   // + mt*16
    const uint32_t a_k16b = ((lane >> 4) & 1) * 16;
    // B x4 addressing: each x4 = 2 n-tiles x 2 k16-halves
    const uint32_t b_row4 = (uint32_t)(warpn * 32 + ((lane >> 4) & 1) * 8 + (lane & 7)); // + np*16
    const uint32_t b_k16b = ((lane >> 3) & 1) * 16;

    for (int kc = 0; kc < nch; kc++) {
        CP_WAIT1();
        __syncthreads();

        if (kc + 2 < nch) {
            issue_stage_load(sb + ((kc + 2) % STAGES) * STAGE_B,
                             A, B, m0, n0, K, kc + 2, t);
        }
        CP_COMMIT();

        const uint32_t tu = sb + (kc % STAGES) * STAGE_B;

#pragma unroll
        for (int k16 = 0; k16 < 4; k16++) {     // 4 x K16 per 64-wide chunk
            uint32_t a[2][4], b[4][2];
#pragma unroll
            for (int mt = 0; mt < 2; mt++) {
                uint32_t bo = (a_row + mt * 16) * 128 + k16 * 32 + a_k16b;
                LDSM_X4(a[mt][0], a[mt][1], a[mt][2], a[mt][3], tu + SWZ(bo));
            }
#pragma unroll
            for (int np = 0; np < 2; np++) {    // each x4 covers 2 n-tiles
                uint32_t bo = (b_row4 + np * 16) * 128 + k16 * 32 + b_k16b;
                LDSM_X4(b[np * 2][0], b[np * 2][1],
                        b[np * 2 + 1][0], b[np * 2 + 1][1],
                        tu + TILE_A_B + SWZ(bo));
            }
#pragma unroll
            for (int mt = 0; mt < 2; mt++)
#pragma unroll
                for (int nt = 0; nt < 4; nt++) MMA16816(acc[mt][nt], a[mt], b[nt]);
        }
    }
    CP_WAIT0();

    const int rbase = lane >> 2;           // 0..7
    const int cbase = (lane & 3) * 2;

    if (EPI == 2) {
        // ---- stage transposed tile in SMEM, then coalesced writeout ----
        __syncthreads();
        float* stg = (float*)smem;         // [64 cols][129] fp32 = 33 KB
#pragma unroll
        for (int mt = 0; mt < 2; mt++) {
#pragma unroll
            for (int nt = 0; nt < 4; nt++) {
                int row = warpm * 32 + mt * 16 + rbase;   // s_local 0..127
                int col = warpn * 32 + nt * 8 + cbase;    // n_local 0..63
                float* d = acc[mt][nt];
                stg[(col + 0) * 129 + row + 0] = d[0];
                stg[(col + 1) * 129 + row + 0] = d[1];
                stg[(col + 0) * 129 + row + 8] = d[2];
                stg[(col + 1) * 129 + row + 8] = d[3];
            }
        }
        __syncthreads();
        const int n_l = t >> 2;            // 0..63
        const int hf  = t & 3;             // s quarter
        const int b   = m0 >> 11;
        const int s0  = (m0 & 2047) + hf * 32;
        const size_t obase = ((size_t)(b * DIM + n0 + n_l)) * SEQ + s0;
#pragma unroll
        for (int j8 = 0; j8 < 4; j8++) {
            ushort hp[8];
#pragma unroll
            for (int e = 0; e < 8; e++) {
                float v = stg[n_l * 129 + hf * 32 + j8 * 8 + e] * escale;
                hp[e] = __half_as_ushort(__float2half_rn(v));
            }
            *(uint4*)&Ch[obase + j8 * 8] = *(uint4*)hp;
        }
        return;
    }

#pragma unroll
    for (int mt = 0; mt < 2; mt++) {
#pragma unroll
        for (int nt = 0; nt < 4; nt++) {
            int row = m0 + warpm * 32 + mt * 16 + rbase;
            int col = n0 + warpn * 32 + nt * 8 + cbase;
            float* d = acc[mt][nt];
            if (EPI == 0) {
                float* Cb = Cf + zb * sC;
                *(float2*)&Cb[(size_t)row * N + col]       = make_float2(d[0], d[1]);
                *(float2*)&Cb[(size_t)(row + 8) * N + col] = make_float2(d[2], d[3]);
            } else {   // EPI == 1 : fp16 store
#pragma unroll
                for (int hrow = 0; hrow < 2; hrow++) {
                    __half h0 = __float2half_rn(d[hrow * 2 + 0] * escale);
                    __half h1 = __float2half_rn(d[hrow * 2 + 1] * escale);
                    size_t idx = (size_t)(row + hrow * 8) * N + col;
                    *(uint32_t*)&Ch[idx] = (uint32_t)__half_as_ushort(h0) |
                                           ((uint32_t)__half_as_ushort(h1) << 16);
                }
            }
        }
    }
}

// ---------------------------------------------------------------------------
// Fused fp32 -> fp16 convert for all 4 inputs in ONE launch.
// ---------------------------------------------------------------------------
#define N4_X  (MQ * DIM / 4)
#define N4_W  (DIM * DIM / 4)

__global__ __launch_bounds__(256) void cvt_all_kernel(
    const float* __restrict__ x,  const float* __restrict__ wq,
    const float* __restrict__ wk, const float* __restrict__ wv,
    __half* __restrict__ X,  __half* __restrict__ Wq,
    __half* __restrict__ Wk, __half* __restrict__ Wv)
{
    int i = blockIdx.x * blockDim.x + threadIdx.x;
    const float* src;  __half* dst;  int j = i;
    if (j < N4_X)                { src = x;  dst = X;  }
    else if ((j -= N4_X) < N4_W) { src = wq; dst = Wq; }
    else if ((j -= N4_W) < N4_W) { src = wk; dst = Wk; }
    else if ((j -= N4_W) < N4_W) { src = wv; dst = Wv; }
    else return;
    float4 v = ((const float4*)src)[j];
    ushort hp[4] = { __half_as_ushort(__float2half_rn(v.x)),
                     __half_as_ushort(__float2half_rn(v.y)),
                     __half_as_ushort(__float2half_rn(v.z)),
                     __half_as_ushort(__float2half_rn(v.w)) };
    ((uint2*)dst)[j] = *(uint2*)hp;
}

// ---------------------------------------------------------------------------
// Softmax over rows of S (pre-scaled via Q), writes P fp16. float4 loads.
// ---------------------------------------------------------------------------
__global__ __launch_bounds__(256) void softmax_kernel(
    const float* __restrict__ S, __half* __restrict__ P)
{
    const float4* row = (const float4*)(S + (size_t)blockIdx.x * SEQ);
    __half* pr = P + (size_t)blockIdx.x * SEQ;
    const int t = threadIdx.x;
    __shared__ float red[256];

    float4 v0 = row[t];
    float4 v1 = row[256 + t];

    float lmax = fmaxf(fmaxf(fmaxf(v0.x, v0.y), fmaxf(v0.z, v0.w)),
                       fmaxf(fmaxf(v1.x, v1.y), fmaxf(v1.z, v1.w)));
    red[t] = lmax;
    __syncthreads();
    for (int s = 128; s > 0; s >>= 1) {
        if (t < s) red[t] = fmaxf(red[t], red[t + s]);
        __syncthreads();
    }
    const float m = red[0];
    __syncthreads();

    v0.x = __expf(v0.x - m);  v0.y = __expf(v0.y - m);
    v0.z = __expf(v0.z - m);  v0.w = __expf(v0.w - m);
    v1.x = __expf(v1.x - m);  v1.y = __expf(v1.y - m);
    v1.z = __expf(v1.z - m);  v1.w = __expf(v1.w - m);
    float lsum = (v0.x + v0.y) + (v0.z + v0.w) + (v1.x + v1.y) + (v1.z + v1.w);
    red[t] = lsum;
    __syncthreads();
    for (int s = 128; s > 0; s >>= 1) {
        if (t < s) red[t] += red[t + s];
        __syncthreads();
    }
    const float inv = 1.0f / red[0];

    ushort h0[4] = { __half_as_ushort(__float2half_rn(v0.x * inv)),
                     __half_as_ushort(__float2half_rn(v0.y * inv)),
                     __half_as_ushort(__float2half_rn(v0.z * inv)),
                     __half_as_ushort(__float2half_rn(v0.w * inv)) };
    ushort h1[4] = { __half_as_ushort(__float2half_rn(v1.x * inv)),
                     __half_as_ushort(__float2half_rn(v1.y * inv)),
                     __half_as_ushort(__float2half_rn(v1.z * inv)),
                     __half_as_ushort(__float2half_rn(v1.w * inv)) };
    ((uint2*)pr)[t]       = *(uint2*)h0;
    ((uint2*)pr)[256 + t] = *(uint2*)h1;
}

// ---------------------------------------------------------------------------
// kernel_launch : x, W_key, W_query, W_value -> context (fp32)
// ---------------------------------------------------------------------------
extern "C" void kernel_launch(void* const* d_in, const int* in_sizes, int n_in,
                              void* d_out, int out_size)
{
    const float* x  = (const float*)d_in[0];
    const float* Wk = (const float*)d_in[1];
    const float* Wq = (const float*)d_in[2];
    const float* Wv = (const float*)d_in[3];
    float* out = (float*)d_out;

    float* S;
    __half *X, *Wqh, *Wkh, *Wvh, *Q, *K, *Vt, *P;
    cudaGetSymbolAddress((void**)&S,   g_S);
    cudaGetSymbolAddress((void**)&X,   g_X);
    cudaGetSymbolAddress((void**)&Wqh, g_Wq);
    cudaGetSymbolAddress((void**)&Wkh, g_Wk);
    cudaGetSymbolAddress((void**)&Wvh, g_Wv);
    cudaGetSymbolAddress((void**)&Q,   g_Q);
    cudaGetSymbolAddress((void**)&K,   g_K);
    cudaGetSymbolAddress((void**)&Vt,  g_Vt);
    cudaGetSymbolAddress((void**)&P,   g_P);

    cudaFuncSetAttribute(gemm_f16<0>, cudaFuncAttributeMaxDynamicSharedMemorySize, GSMEM);
    cudaFuncSetAttribute(gemm_f16<1>, cudaFuncAttributeMaxDynamicSharedMemorySize, GSMEM);
    cudaFuncSetAttribute(gemm_f16<2>, cudaFuncAttributeMaxDynamicSharedMemorySize, GSMEM);

    // 1) convert all inputs to fp16 in one launch
    {
        int total = N4_X + 3 * N4_W;
        cvt_all_kernel<<<(total + 255) / 256, 256>>>(x, Wq, Wk, Wv,
                                                     X, Wqh, Wkh, Wvh);
    }

    // 2) projections: Q (scaled by 1/32), K, V (transpose-store)
    {
        dim3 grid(DIM / 64, MQ / 128, 1);
        gemm_f16<1><<<grid, 256, GSMEM>>>(X, Wqh, nullptr, Q,
            MQ, DIM, DIM, 0, 0, 0, 1.0f / 32.0f);
        gemm_f16<1><<<grid, 256, GSMEM>>>(X, Wkh, nullptr, K,
            MQ, DIM, DIM, 0, 0, 0, 1.0f);
        gemm_f16<2><<<grid, 256, GSMEM>>>(X, Wvh, nullptr, Vt,
            MQ, DIM, DIM, 0, 0, 0, 1.0f);
    }

    // 3) scores[b] = Qs[b] * K[b]^T  (already scaled) -> fp32 S
    {
        dim3 grid(SEQ / 64, SEQ / 128, BATCH);
        gemm_f16<0><<<grid, 256, GSMEM>>>(Q, K, S, nullptr,
            SEQ, SEQ, DIM,
            (size_t)SEQ * DIM, (size_t)SEQ * DIM, (size_t)SEQ * SEQ, 1.0f);
    }

    // 4) softmax rows -> P fp16
    softmax_kernel<<<BATCH * SEQ, 256>>>(S, P);

    // 5) context[b] = P[b] * Vt[b]^T -> out fp32
    {
        dim3 grid(DIM / 64, SEQ / 128, BATCH);
        gemm_f16<0><<<grid, 256, GSMEM>>>(P, Vt, out, nullptr,
            SEQ, DIM, SEQ,
            (size_t)SEQ * SEQ, (size_t)DIM * SEQ, (size_t)SEQ * DIM, 1.0f);
    }
}